// round 6
// baseline (speedup 1.0000x reference)
#include <cuda_runtime.h>
#include <math.h>

typedef unsigned long long ull;

// ---------------- scratch (device globals; no allocs allowed) ----------------
__device__ float g_K1[32 * 32];               // [co][tap32] (25 used, padded)
__device__ float g_K2p[32 * 32 * 52];         // [co/2][ci][26 taps][2] pair layout
__device__ float g_out1[4096 * 32 * 14 * 14]; // conv1+pool output
__device__ float g_out2[4096 * 64 * 7 * 7];   // conv2+pool output (= fc1 input)
__device__ float g_h[4096 * 128];             // fc1 output

__device__ __forceinline__ ull ffma2(ull a, ull b, ull c) {
    ull d;
    asm("fma.rn.f32x2 %0, %1, %2, %3;" : "=l"(d) : "l"(a), "l"(b), "l"(c));
    return d;
}

// ---------------- DCLS kernel construction (gather, deterministic) ----------
__global__ void build_dcls(const float* __restrict__ w, const float* __restrict__ p,
                           int Co, int Ci, int Kc, int layer) {
    int t = blockIdx.x * blockDim.x + threadIdx.x;
    if (t >= Co * Ci) return;
    float acc[25];
#pragma unroll
    for (int j = 0; j < 25; j++) acc[j] = 0.f;
    int base = t * Kc;
    int pstride = Co * Ci * Kc;
    for (int kc = 0; kc < Kc; kc++) {
        float ww = w[base + kc];
        float p1 = p[base + kc];
        float p2 = p[pstride + base + kc];
        p1 = fminf(fmaxf(p1, -2.f), 2.f) + 2.f;
        p2 = fminf(fmaxf(p2, -2.f), 2.f) + 2.f;
        int i1 = (int)floorf(p1), i2 = (int)floorf(p2);
        float r1 = p1 - (float)i1, r2 = p2 - (float)i2;
        acc[i1 * 5 + i2] += ww * (1.f - r1) * (1.f - r2);
        if (i1 + 1 < 5)               acc[(i1 + 1) * 5 + i2]     += ww * r1 * (1.f - r2);
        if (i2 + 1 < 5)               acc[i1 * 5 + (i2 + 1)]     += ww * (1.f - r1) * r2;
        if (i1 + 1 < 5 && i2 + 1 < 5) acc[(i1 + 1) * 5 + i2 + 1] += ww * r1 * r2;
    }
    if (layer == 0) {
        float* o = g_K1 + t * 32;
#pragma unroll
        for (int j = 0; j < 32; j++) o[j] = (j < 25) ? acc[j] : 0.f;
    } else {
        int co = t >> 5;          // Ci = 32
        int ci = t & 31;
        float* o = g_K2p + (((co >> 1) * 32) + ci) * 52 + (co & 1);
#pragma unroll
        for (int j = 0; j < 25; j++) o[j * 2] = acc[j];
    }
}

// ---------------- conv1 (1->32, 5x5, pad2) + bias + relu + maxpool2 ---------
__global__ __launch_bounds__(256) void conv1_pool(const float* __restrict__ x,
                                                  const float* __restrict__ b1) {
    __shared__ float s_in[32 * 33];
    __shared__ float s_w[32 * 32];
    int b = blockIdx.x;
    int tid = threadIdx.x;
    for (int i = tid; i < 32 * 33; i += 256) s_in[i] = 0.f;
    for (int i = tid; i < 32 * 32; i += 256) s_w[i] = g_K1[i];
    __syncthreads();
    const float* xb = x + b * 784;
    for (int i = tid; i < 784; i += 256) {
        int y = i / 28, xx = i - y * 28;
        s_in[(y + 2) * 33 + (xx + 2)] = xb[i];
    }
    __syncthreads();

    int co = tid >> 3;
    int s  = tid & 7;
    float wreg[25];
#pragma unroll
    for (int j = 0; j < 25; j++) wreg[j] = s_w[co * 32 + j];
    float bias = b1[co];
    float* ob = g_out1 + (b * 32 + co) * 196;

    for (int pos = s; pos < 196; pos += 8) {
        int oy = pos / 14, ox = pos - oy * 14;
        const float* pbase = s_in + (2 * oy) * 33 + 2 * ox;
        float xin[6][6];
#pragma unroll
        for (int r = 0; r < 6; r++)
#pragma unroll
            for (int c = 0; c < 6; c++) xin[r][c] = pbase[r * 33 + c];
        float a00 = 0.f, a01 = 0.f, a10 = 0.f, a11 = 0.f;
#pragma unroll
        for (int ky = 0; ky < 5; ky++)
#pragma unroll
            for (int kx = 0; kx < 5; kx++) {
                float w = wreg[ky * 5 + kx];
                a00 = fmaf(w, xin[ky][kx],         a00);
                a01 = fmaf(w, xin[ky][kx + 1],     a01);
                a10 = fmaf(w, xin[ky + 1][kx],     a10);
                a11 = fmaf(w, xin[ky + 1][kx + 1], a11);
            }
        float m = fmaxf(fmaxf(a00, a01), fmaxf(a10, a11));
        ob[pos] = fmaxf(m + bias, 0.f);
    }
}

// ---------------- conv2 (32->64) f32x2 version ------------------------------
// one block per image, 448 threads = 16 co-groups x 7 oy x 4 ox-pairs.
// Each thread: 2 co-PAIRS (4 co, paired in f32x2 lanes) x 2x4 conv pixels.
// Input tile stored DUPLICATED in smem so LDS.64 yields (v,v) broadcast pairs.
__device__ __forceinline__ void loadx(ull* D, const float* xp, int R) {
#pragma unroll
    for (int o = 0; o < 8; o++) D[o] = *(const ull*)(xp + R * 40 + 2 * o);
}
__device__ __forceinline__ void loadw(ull W[2][5], const float* w0p, const float* w1p, int KY) {
#pragma unroll
    for (int kx = 0; kx < 5; kx++) {
        W[0][kx] = *(const ull*)(w0p + (KY * 5 + kx) * 2);
        W[1][kx] = *(const ull*)(w1p + (KY * 5 + kx) * 2);
    }
}
__device__ __forceinline__ void fmas(ull acc[2][8], ull W[2][5], ull* R0, ull* R1) {
#pragma unroll
    for (int kx = 0; kx < 5; kx++)
#pragma unroll
        for (int cx = 0; cx < 4; cx++) {
            acc[0][cx]     = ffma2(W[0][kx], R0[cx + kx], acc[0][cx]);
            acc[1][cx]     = ffma2(W[1][kx], R0[cx + kx], acc[1][cx]);
            acc[0][4 + cx] = ffma2(W[0][kx], R1[cx + kx], acc[0][4 + cx]);
            acc[1][4 + cx] = ffma2(W[1][kx], R1[cx + kx], acc[1][4 + cx]);
        }
}

__global__ __launch_bounds__(448, 1) void conv2_pool(const float* __restrict__ b2) {
    extern __shared__ float s2[];     // 32 ch * 18 rows * 40 floats (dup cols) = 90KB
    int b = blockIdx.x;
    int tid = threadIdx.x;
    for (int i = tid; i < 32 * 18 * 40; i += 448) s2[i] = 0.f;
    __syncthreads();
    const float* inb = g_out1 + b * 6272;
    for (int i = tid; i < 6272; i += 448) {
        int ci = i / 196;
        int r = i - ci * 196;
        int y = r / 14, xx = r - y * 14;
        float v = inb[i];
        *(float2*)(s2 + ci * 720 + (y + 2) * 40 + (xx + 2) * 2) = make_float2(v, v);
    }
    __syncthreads();

    int g   = tid / 28;          // 0..15 -> co group (4 consecutive co = 2 pairs)
    int rem = tid - g * 28;
    int oy  = rem >> 2;          // 0..6
    int oxp = rem & 3;           // 0..3 (conv cols 4*oxp .. 4*oxp+3)

    ull acc[2][8];
#pragma unroll
    for (int c = 0; c < 2; c++)
#pragma unroll
        for (int j = 0; j < 8; j++) acc[c][j] = 0ull;

    const float* xbase = s2 + (2 * oy) * 40 + oxp * 8;
    const float* wb0 = g_K2p + (g * 2) * (32 * 52);      // pair cp0 = 2g
    const float* wb1 = wb0 + 32 * 52;                    // pair cp0+1

#pragma unroll 1
    for (int ci = 0; ci < 32; ci++) {
        const float* xp  = xbase + ci * 720;
        const float* w0p = wb0 + ci * 52;
        const float* w1p = wb1 + ci * 52;
        ull xA[8], xB[8], wA[2][5], wB[2][5];
        loadx(xA, xp, 0); loadw(wA, w0p, w1p, 0);
        loadx(xB, xp, 1); loadw(wB, w0p, w1p, 1);
        fmas(acc, wA, xA, xB);            // ky=0: rows 0,1
        loadx(xA, xp, 2); loadw(wA, w0p, w1p, 2);
        fmas(acc, wB, xB, xA);            // ky=1: rows 1,2
        loadx(xB, xp, 3); loadw(wB, w0p, w1p, 3);
        fmas(acc, wA, xA, xB);            // ky=2: rows 2,3
        loadx(xA, xp, 4); loadw(wA, w0p, w1p, 4);
        fmas(acc, wB, xB, xA);            // ky=3: rows 3,4
        loadx(xB, xp, 5);
        fmas(acc, wA, xA, xB);            // ky=4: rows 4,5
    }

    // bias + relu + 2x2 maxpool; acc lanes: .x = co even, .y = co odd
    int b64 = b * 64;
#pragma unroll
    for (int c = 0; c < 2; c++) {
        int co_e = g * 4 + c * 2;
        float be = b2[co_e], bo = b2[co_e + 1];
#pragma unroll
        for (int px = 0; px < 2; px++) {
            int ox = 2 * oxp + px;
            if (ox < 7) {
                float2 v0 = *(float2*)&acc[c][2 * px];
                float2 v1 = *(float2*)&acc[c][2 * px + 1];
                float2 v2 = *(float2*)&acc[c][4 + 2 * px];
                float2 v3 = *(float2*)&acc[c][4 + 2 * px + 1];
                float me = fmaxf(fmaxf(v0.x, v1.x), fmaxf(v2.x, v3.x));
                float mo = fmaxf(fmaxf(v0.y, v1.y), fmaxf(v2.y, v3.y));
                g_out2[((b64 + co_e) * 7 + oy) * 7 + ox]     = fmaxf(me + be, 0.f);
                g_out2[((b64 + co_e + 1) * 7 + oy) * 7 + ox] = fmaxf(mo + bo, 0.f);
            }
        }
    }
}

// ---------------- fc1: (4096,3136) x (128,3136)^T + bias, relu -> g_h -------
__global__ __launch_bounds__(256) void fc1_gemm(const float* __restrict__ W,
                                                const float* __restrict__ bias) {
    __shared__ float As[32][64];
    __shared__ float Bs[32][64];
    int tid = threadIdx.x;
    int row0 = blockIdx.x * 64;
    int col0 = blockIdx.y * 64;
    const float* A = g_out2;

    int lr  = tid >> 2;
    int lk4 = (tid & 3) << 3;
    int tm  = tid >> 4;
    int tn  = tid & 15;

    float acc[4][4];
#pragma unroll
    for (int i = 0; i < 4; i++)
#pragma unroll
        for (int j = 0; j < 4; j++) acc[i][j] = 0.f;

    for (int k0 = 0; k0 < 3136; k0 += 32) {
        float4 a0 = *(const float4*)(A + (row0 + lr) * 3136 + k0 + lk4);
        float4 a1 = *(const float4*)(A + (row0 + lr) * 3136 + k0 + lk4 + 4);
        float4 w0 = *(const float4*)(W + (col0 + lr) * 3136 + k0 + lk4);
        float4 w1 = *(const float4*)(W + (col0 + lr) * 3136 + k0 + lk4 + 4);
        __syncthreads();
        As[lk4 + 0][lr] = a0.x; As[lk4 + 1][lr] = a0.y;
        As[lk4 + 2][lr] = a0.z; As[lk4 + 3][lr] = a0.w;
        As[lk4 + 4][lr] = a1.x; As[lk4 + 5][lr] = a1.y;
        As[lk4 + 6][lr] = a1.z; As[lk4 + 7][lr] = a1.w;
        Bs[lk4 + 0][lr] = w0.x; Bs[lk4 + 1][lr] = w0.y;
        Bs[lk4 + 2][lr] = w0.z; Bs[lk4 + 3][lr] = w0.w;
        Bs[lk4 + 4][lr] = w1.x; Bs[lk4 + 5][lr] = w1.y;
        Bs[lk4 + 6][lr] = w1.z; Bs[lk4 + 7][lr] = w1.w;
        __syncthreads();
#pragma unroll
        for (int kk = 0; kk < 32; kk++) {
            float4 av = *(const float4*)&As[kk][tm * 4];
            float4 bv = *(const float4*)&Bs[kk][tn * 4];
            acc[0][0] = fmaf(av.x, bv.x, acc[0][0]);
            acc[0][1] = fmaf(av.x, bv.y, acc[0][1]);
            acc[0][2] = fmaf(av.x, bv.z, acc[0][2]);
            acc[0][3] = fmaf(av.x, bv.w, acc[0][3]);
            acc[1][0] = fmaf(av.y, bv.x, acc[1][0]);
            acc[1][1] = fmaf(av.y, bv.y, acc[1][1]);
            acc[1][2] = fmaf(av.y, bv.z, acc[1][2]);
            acc[1][3] = fmaf(av.y, bv.w, acc[1][3]);
            acc[2][0] = fmaf(av.z, bv.x, acc[2][0]);
            acc[2][1] = fmaf(av.z, bv.y, acc[2][1]);
            acc[2][2] = fmaf(av.z, bv.z, acc[2][2]);
            acc[2][3] = fmaf(av.z, bv.w, acc[2][3]);
            acc[3][0] = fmaf(av.w, bv.x, acc[3][0]);
            acc[3][1] = fmaf(av.w, bv.y, acc[3][1]);
            acc[3][2] = fmaf(av.w, bv.z, acc[3][2]);
            acc[3][3] = fmaf(av.w, bv.w, acc[3][3]);
        }
    }
#pragma unroll
    for (int i = 0; i < 4; i++)
#pragma unroll
        for (int j = 0; j < 4; j++) {
            int rr = row0 + tm * 4 + i;
            int cc = col0 + tn * 4 + j;
            g_h[rr * 128 + cc] = fmaxf(acc[i][j] + bias[cc], 0.f);
        }
}

// ---------------- fc2: (4096,128) x (10,128)^T + bias -> out ----------------
__global__ void fc2_gemv(const float* __restrict__ W, const float* __restrict__ bias,
                         float* __restrict__ out, int B) {
    int idx = blockIdx.x * blockDim.x + threadIdx.x;
    if (idx >= B * 10) return;
    int row = idx / 10;
    int j = idx - row * 10;
    const float* h = g_h + row * 128;
    const float* w = W + j * 128;
    float s = bias[j];
#pragma unroll
    for (int k = 0; k < 128; k += 4) {
        float4 hv = *(const float4*)(h + k);
        float4 wv = *(const float4*)(w + k);
        s = fmaf(hv.x, wv.x, s);
        s = fmaf(hv.y, wv.y, s);
        s = fmaf(hv.z, wv.z, s);
        s = fmaf(hv.w, wv.w, s);
    }
    out[idx] = s;
}

// ---------------- launch -----------------------------------------------------
extern "C" void kernel_launch(void* const* d_in, const int* in_sizes, int n_in,
                              void* d_out, int out_size) {
    const float* x     = (const float*)d_in[0];
    const float* w1    = (const float*)d_in[1];
    const float* p1    = (const float*)d_in[2];
    const float* b1    = (const float*)d_in[3];
    const float* w2    = (const float*)d_in[4];
    const float* p2    = (const float*)d_in[5];
    const float* b2    = (const float*)d_in[6];
    const float* fc1w  = (const float*)d_in[7];
    const float* fc1b  = (const float*)d_in[8];
    const float* fc2w  = (const float*)d_in[9];
    const float* fc2b  = (const float*)d_in[10];
    float* out = (float*)d_out;

    int B = in_sizes[0] / 784;   // 4096
    const int smem2 = 32 * 18 * 40 * 4;   // 92160 B

    static int attr_done = 0;
    if (!attr_done) {
        cudaFuncSetAttribute(conv2_pool, cudaFuncAttributeMaxDynamicSharedMemorySize, smem2);
        attr_done = 1;
    }

    build_dcls<<<1, 64>>>(w1, p1, 32, 1, 16, 0);
    build_dcls<<<8, 256>>>(w2, p2, 64, 32, 32, 1);
    conv1_pool<<<B, 256>>>(x, b1);
    conv2_pool<<<B, 448, smem2>>>(b2);
    dim3 g1(B / 64, 2);
    fc1_gemm<<<g1, 256>>>(fc1w, fc1b);
    fc2_gemv<<<(B * 10 + 255) / 256, 256>>>(fc2w, fc2b, out, B);
}

// round 12
// speedup vs baseline: 1.1064x; 1.1064x over previous
#include <cuda_runtime.h>
#include <math.h>

typedef unsigned long long ull;

// ---------------- scratch (device globals; no allocs allowed) ----------------
__device__ float g_K1[32 * 32];               // [co][tap32] (25 used, padded)
__device__ float g_K2w[32 * 25 * 2 * 32];     // [ci][tap][c][cog][2] pair layout
__device__ float g_out1[4096 * 32 * 14 * 14]; // conv1+pool output
__device__ float g_out2[4096 * 64 * 7 * 7];   // conv2+pool output (= fc1 input)
__device__ float g_h[4096 * 128];             // fc1 output

__device__ __forceinline__ ull ffma2(ull a, ull b, ull c) {
    ull d;
    asm("fma.rn.f32x2 %0, %1, %2, %3;" : "=l"(d) : "l"(a), "l"(b), "l"(c));
    return d;
}

// ---------------- DCLS kernel construction (gather, deterministic) ----------
__global__ void build_dcls(const float* __restrict__ w, const float* __restrict__ p,
                           int Co, int Ci, int Kc, int layer) {
    int t = blockIdx.x * blockDim.x + threadIdx.x;
    if (t >= Co * Ci) return;
    float acc[25];
#pragma unroll
    for (int j = 0; j < 25; j++) acc[j] = 0.f;
    int base = t * Kc;
    int pstride = Co * Ci * Kc;
    for (int kc = 0; kc < Kc; kc++) {
        float ww = w[base + kc];
        float p1 = p[base + kc];
        float p2 = p[pstride + base + kc];
        p1 = fminf(fmaxf(p1, -2.f), 2.f) + 2.f;
        p2 = fminf(fmaxf(p2, -2.f), 2.f) + 2.f;
        int i1 = (int)floorf(p1), i2 = (int)floorf(p2);
        float r1 = p1 - (float)i1, r2 = p2 - (float)i2;
        acc[i1 * 5 + i2] += ww * (1.f - r1) * (1.f - r2);
        if (i1 + 1 < 5)               acc[(i1 + 1) * 5 + i2]     += ww * r1 * (1.f - r2);
        if (i2 + 1 < 5)               acc[i1 * 5 + (i2 + 1)]     += ww * (1.f - r1) * r2;
        if (i1 + 1 < 5 && i2 + 1 < 5) acc[(i1 + 1) * 5 + i2 + 1] += ww * r1 * r2;
    }
    if (layer == 0) {
        float* o = g_K1 + t * 32;
#pragma unroll
        for (int j = 0; j < 32; j++) o[j] = (j < 25) ? acc[j] : 0.f;
    } else {
        int co = t >> 5;          // Ci = 32
        int ci = t & 31;
        int cog = co >> 2;        // 0..15
        int c   = (co >> 1) & 1;  // pair-within-group
        int e   = co & 1;         // lane parity within pair
#pragma unroll
        for (int j = 0; j < 25; j++)
            g_K2w[((ci * 25 + j) * 2 + c) * 32 + cog * 2 + e] = acc[j];
    }
}

// ---------------- conv1 (1->32, 5x5, pad2) + bias + relu + maxpool2 ---------
__global__ __launch_bounds__(256) void conv1_pool(const float* __restrict__ x,
                                                  const float* __restrict__ b1) {
    __shared__ float s_in[32 * 33];
    __shared__ float s_w[32 * 32];
    int b = blockIdx.x;
    int tid = threadIdx.x;
    for (int i = tid; i < 32 * 33; i += 256) s_in[i] = 0.f;
    for (int i = tid; i < 32 * 32; i += 256) s_w[i] = g_K1[i];
    __syncthreads();
    const float* xb = x + b * 784;
    for (int i = tid; i < 784; i += 256) {
        int y = i / 28, xx = i - y * 28;
        s_in[(y + 2) * 33 + (xx + 2)] = xb[i];
    }
    __syncthreads();

    int co = tid >> 3;
    int s  = tid & 7;
    float wreg[25];
#pragma unroll
    for (int j = 0; j < 25; j++) wreg[j] = s_w[co * 32 + j];
    float bias = b1[co];
    float* ob = g_out1 + (b * 32 + co) * 196;

    for (int pos = s; pos < 196; pos += 8) {
        int oy = pos / 14, ox = pos - oy * 14;
        const float* pbase = s_in + (2 * oy) * 33 + 2 * ox;
        float xin[6][6];
#pragma unroll
        for (int r = 0; r < 6; r++)
#pragma unroll
            for (int c = 0; c < 6; c++) xin[r][c] = pbase[r * 33 + c];
        float a00 = 0.f, a01 = 0.f, a10 = 0.f, a11 = 0.f;
#pragma unroll
        for (int ky = 0; ky < 5; ky++)
#pragma unroll
            for (int kx = 0; kx < 5; kx++) {
                float w = wreg[ky * 5 + kx];
                a00 = fmaf(w, xin[ky][kx],         a00);
                a01 = fmaf(w, xin[ky][kx + 1],     a01);
                a10 = fmaf(w, xin[ky + 1][kx],     a10);
                a11 = fmaf(w, xin[ky + 1][kx + 1], a11);
            }
        float m = fmaxf(fmaxf(a00, a01), fmaxf(a10, a11));
        ob[pos] = fmaxf(m + bias, 0.f);
    }
}

// ---------------- conv2 (32->64) f32x2, warp-over-channels mapping ----------
// 448 threads = 14 warps. lane = cog*2 + ps (cog: 16 co-groups of 4 co = 2 pairs),
// pixel-position pp = warp*2+ps (28 positions = 7 oy x 4 ox-quads).
// Input LDS.64: 2 distinct addrs/warp -> conflict-free broadcast.
// Weight LDG.64 from global: 16 distinct consecutive 8B addrs/warp = one 128B line,
// same addresses for every CTA -> L1/L2 resident.
__device__ __forceinline__ void loadx(ull* D, const float* xp, int R) {
#pragma unroll
    for (int o = 0; o < 8; o++) D[o] = *(const ull*)(xp + R * 40 + 2 * o);
}
__device__ __forceinline__ void loadw(ull W[2][5], const float* __restrict__ wp, int KY) {
#pragma unroll
    for (int kx = 0; kx < 5; kx++) {
        W[0][kx] = *(const ull*)(wp + ((KY * 5 + kx) * 2 + 0) * 32);
        W[1][kx] = *(const ull*)(wp + ((KY * 5 + kx) * 2 + 1) * 32);
    }
}
__device__ __forceinline__ void fmas(ull acc[2][8], ull W[2][5], ull* R0, ull* R1) {
#pragma unroll
    for (int kx = 0; kx < 5; kx++)
#pragma unroll
        for (int cx = 0; cx < 4; cx++) {
            acc[0][cx]     = ffma2(W[0][kx], R0[cx + kx], acc[0][cx]);
            acc[1][cx]     = ffma2(W[1][kx], R0[cx + kx], acc[1][cx]);
            acc[0][4 + cx] = ffma2(W[0][kx], R1[cx + kx], acc[0][4 + cx]);
            acc[1][4 + cx] = ffma2(W[1][kx], R1[cx + kx], acc[1][4 + cx]);
        }
}

__global__ __launch_bounds__(448, 1) void conv2_pool(const float* __restrict__ b2) {
    extern __shared__ float s_in[];    // 32 ch * 18 rows * 40 floats (dup) = 92160B
    int b = blockIdx.x;
    int tid = threadIdx.x;

    for (int i = tid; i < 32 * 18 * 40; i += 448) s_in[i] = 0.f;
    __syncthreads();
    const float* inb = g_out1 + b * 6272;
    for (int i = tid; i < 6272; i += 448) {
        int ci = i / 196;
        int r = i - ci * 196;
        int y = r / 14, xx = r - y * 14;
        float v = inb[i];
        *(float2*)(s_in + ci * 720 + (y + 2) * 40 + (xx + 2) * 2) = make_float2(v, v);
    }
    __syncthreads();

    int wrp  = tid >> 5;          // 0..13
    int lane = tid & 31;
    int cog  = lane >> 1;         // 0..15
    int ps   = lane & 1;
    int pp   = wrp * 2 + ps;      // 0..27
    int oy   = pp >> 2;           // 0..6
    int oxp  = pp & 3;            // 0..3

    ull acc[2][8];
#pragma unroll
    for (int c = 0; c < 2; c++)
#pragma unroll
        for (int j = 0; j < 8; j++) acc[c][j] = 0ull;

    const float* xbase = s_in + (2 * oy) * 40 + oxp * 8;
    const float* wbase = g_K2w + cog * 2;

#pragma unroll 1
    for (int ci = 0; ci < 32; ci++) {
        const float* xp = xbase + ci * 720;
        const float* wp = wbase + ci * 25 * 64;
        ull xA[8], xB[8], wA[2][5], wB[2][5];
        loadx(xA, xp, 0); loadw(wA, wp, 0);
        loadx(xB, xp, 1); loadw(wB, wp, 1);
        fmas(acc, wA, xA, xB);            // ky=0: rows 0,1
        loadx(xA, xp, 2); loadw(wA, wp, 2);
        fmas(acc, wB, xB, xA);            // ky=1: rows 1,2
        loadx(xB, xp, 3); loadw(wB, wp, 3);
        fmas(acc, wA, xA, xB);            // ky=2: rows 2,3
        loadx(xA, xp, 4); loadw(wA, wp, 4);
        fmas(acc, wB, xB, xA);            // ky=3: rows 3,4
        loadx(xB, xp, 5);
        fmas(acc, wA, xA, xB);            // ky=4: rows 4,5
    }

    // bias + relu + 2x2 maxpool; acc lanes: .x = co even, .y = co odd
    int b64 = b * 64;
#pragma unroll
    for (int c = 0; c < 2; c++) {
        int co_e = cog * 4 + c * 2;
        float be = b2[co_e], bo = b2[co_e + 1];
#pragma unroll
        for (int px = 0; px < 2; px++) {
            int ox = 2 * oxp + px;
            if (ox < 7) {
                float2 v0 = *(float2*)&acc[c][2 * px];
                float2 v1 = *(float2*)&acc[c][2 * px + 1];
                float2 v2 = *(float2*)&acc[c][4 + 2 * px];
                float2 v3 = *(float2*)&acc[c][4 + 2 * px + 1];
                float me = fmaxf(fmaxf(v0.x, v1.x), fmaxf(v2.x, v3.x));
                float mo = fmaxf(fmaxf(v0.y, v1.y), fmaxf(v2.y, v3.y));
                g_out2[((b64 + co_e) * 7 + oy) * 7 + ox]     = fmaxf(me + be, 0.f);
                g_out2[((b64 + co_e + 1) * 7 + oy) * 7 + ox] = fmaxf(mo + bo, 0.f);
            }
        }
    }
}

// ---------------- fc1: (4096,3136) x (128,3136)^T + bias, relu -> g_h -------
__global__ __launch_bounds__(256) void fc1_gemm(const float* __restrict__ W,
                                                const float* __restrict__ bias) {
    __shared__ float As[32][64];
    __shared__ float Bs[32][64];
    int tid = threadIdx.x;
    int row0 = blockIdx.x * 64;
    int col0 = blockIdx.y * 64;
    const float* A = g_out2;

    int lr  = tid >> 2;
    int lk4 = (tid & 3) << 3;
    int tm  = tid >> 4;
    int tn  = tid & 15;

    float acc[4][4];
#pragma unroll
    for (int i = 0; i < 4; i++)
#pragma unroll
        for (int j = 0; j < 4; j++) acc[i][j] = 0.f;

    for (int k0 = 0; k0 < 3136; k0 += 32) {
        float4 a0 = *(const float4*)(A + (row0 + lr) * 3136 + k0 + lk4);
        float4 a1 = *(const float4*)(A + (row0 + lr) * 3136 + k0 + lk4 + 4);
        float4 w0 = *(const float4*)(W + (col0 + lr) * 3136 + k0 + lk4);
        float4 w1 = *(const float4*)(W + (col0 + lr) * 3136 + k0 + lk4 + 4);
        __syncthreads();
        As[lk4 + 0][lr] = a0.x; As[lk4 + 1][lr] = a0.y;
        As[lk4 + 2][lr] = a0.z; As[lk4 + 3][lr] = a0.w;
        As[lk4 + 4][lr] = a1.x; As[lk4 + 5][lr] = a1.y;
        As[lk4 + 6][lr] = a1.z; As[lk4 + 7][lr] = a1.w;
        Bs[lk4 + 0][lr] = w0.x; Bs[lk4 + 1][lr] = w0.y;
        Bs[lk4 + 2][lr] = w0.z; Bs[lk4 + 3][lr] = w0.w;
        Bs[lk4 + 4][lr] = w1.x; Bs[lk4 + 5][lr] = w1.y;
        Bs[lk4 + 6][lr] = w1.z; Bs[lk4 + 7][lr] = w1.w;
        __syncthreads();
#pragma unroll
        for (int kk = 0; kk < 32; kk++) {
            float4 av = *(const float4*)&As[kk][tm * 4];
            float4 bv = *(const float4*)&Bs[kk][tn * 4];
            acc[0][0] = fmaf(av.x, bv.x, acc[0][0]);
            acc[0][1] = fmaf(av.x, bv.y, acc[0][1]);
            acc[0][2] = fmaf(av.x, bv.z, acc[0][2]);
            acc[0][3] = fmaf(av.x, bv.w, acc[0][3]);
            acc[1][0] = fmaf(av.y, bv.x, acc[1][0]);
            acc[1][1] = fmaf(av.y, bv.y, acc[1][1]);
            acc[1][2] = fmaf(av.y, bv.z, acc[1][2]);
            acc[1][3] = fmaf(av.y, bv.w, acc[1][3]);
            acc[2][0] = fmaf(av.z, bv.x, acc[2][0]);
            acc[2][1] = fmaf(av.z, bv.y, acc[2][1]);
            acc[2][2] = fmaf(av.z, bv.z, acc[2][2]);
            acc[2][3] = fmaf(av.z, bv.w, acc[2][3]);
            acc[3][0] = fmaf(av.w, bv.x, acc[3][0]);
            acc[3][1] = fmaf(av.w, bv.y, acc[3][1]);
            acc[3][2] = fmaf(av.w, bv.z, acc[3][2]);
            acc[3][3] = fmaf(av.w, bv.w, acc[3][3]);
        }
    }
#pragma unroll
    for (int i = 0; i < 4; i++)
#pragma unroll
        for (int j = 0; j < 4; j++) {
            int rr = row0 + tm * 4 + i;
            int cc = col0 + tn * 4 + j;
            g_h[rr * 128 + cc] = fmaxf(acc[i][j] + bias[cc], 0.f);
        }
}

// ---------------- fc2: (4096,128) x (10,128)^T + bias -> out ----------------
__global__ void fc2_gemv(const float* __restrict__ W, const float* __restrict__ bias,
                         float* __restrict__ out, int B) {
    int idx = blockIdx.x * blockDim.x + threadIdx.x;
    if (idx >= B * 10) return;
    int row = idx / 10;
    int j = idx - row * 10;
    const float* h = g_h + row * 128;
    const float* w = W + j * 128;
    float s = bias[j];
#pragma unroll
    for (int k = 0; k < 128; k += 4) {
        float4 hv = *(const float4*)(h + k);
        float4 wv = *(const float4*)(w + k);
        s = fmaf(hv.x, wv.x, s);
        s = fmaf(hv.y, wv.y, s);
        s = fmaf(hv.z, wv.z, s);
        s = fmaf(hv.w, wv.w, s);
    }
    out[idx] = s;
}

// ---------------- launch -----------------------------------------------------
extern "C" void kernel_launch(void* const* d_in, const int* in_sizes, int n_in,
                              void* d_out, int out_size) {
    const float* x     = (const float*)d_in[0];
    const float* w1    = (const float*)d_in[1];
    const float* p1    = (const float*)d_in[2];
    const float* b1    = (const float*)d_in[3];
    const float* w2    = (const float*)d_in[4];
    const float* p2    = (const float*)d_in[5];
    const float* b2    = (const float*)d_in[6];
    const float* fc1w  = (const float*)d_in[7];
    const float* fc1b  = (const float*)d_in[8];
    const float* fc2w  = (const float*)d_in[9];
    const float* fc2b  = (const float*)d_in[10];
    float* out = (float*)d_out;

    int B = in_sizes[0] / 784;   // 4096
    const int smem2 = 32 * 18 * 40 * 4;   // 92160 B (R6-proven size)

    static int attr_done = 0;
    if (!attr_done) {
        cudaFuncSetAttribute(conv2_pool, cudaFuncAttributeMaxDynamicSharedMemorySize, smem2);
        attr_done = 1;
    }

    build_dcls<<<1, 64>>>(w1, p1, 32, 1, 16, 0);
    build_dcls<<<8, 256>>>(w2, p2, 64, 32, 32, 1);
    conv1_pool<<<B, 256>>>(x, b1);
    conv2_pool<<<B, 448, smem2>>>(b2);
    dim3 g1(B / 64, 2);
    fc1_gemm<<<g1, 256>>>(fc1w, fc1b);
    fc2_gemv<<<(B * 10 + 255) / 256, 256>>>(fc2w, fc2b, out, B);
}

// round 13
// speedup vs baseline: 1.1360x; 1.0268x over previous
#include <cuda_runtime.h>
#include <math.h>

typedef unsigned long long ull;

// ---------------- scratch (device globals; no allocs allowed) ----------------
__device__ float g_K1[32 * 32];               // [co][tap32] (25 used, padded)
__device__ float g_K2w[32 * 25 * 2 * 32];     // [ci][tap][c][cog][2] pair layout
__device__ float g_out1[4096 * 32 * 14 * 14]; // conv1+pool output
__device__ float g_out2[4096 * 64 * 7 * 7];   // conv2+pool output (= fc1 input)
__device__ float g_h[4096 * 128];             // fc1 output

__device__ __forceinline__ ull ffma2(ull a, ull b, ull c) {
    ull d;
    asm("fma.rn.f32x2 %0, %1, %2, %3;" : "=l"(d) : "l"(a), "l"(b), "l"(c));
    return d;
}
__device__ __forceinline__ ull dup2(float v) {
    float2 t = make_float2(v, v);
    return *reinterpret_cast<ull*>(&t);
}

// ---------------- DCLS kernel construction (gather, deterministic) ----------
__global__ void build_dcls(const float* __restrict__ w, const float* __restrict__ p,
                           int Co, int Ci, int Kc, int layer) {
    int t = blockIdx.x * blockDim.x + threadIdx.x;
    if (t >= Co * Ci) return;
    float acc[25];
#pragma unroll
    for (int j = 0; j < 25; j++) acc[j] = 0.f;
    int base = t * Kc;
    int pstride = Co * Ci * Kc;
    for (int kc = 0; kc < Kc; kc++) {
        float ww = w[base + kc];
        float p1 = p[base + kc];
        float p2 = p[pstride + base + kc];
        p1 = fminf(fmaxf(p1, -2.f), 2.f) + 2.f;
        p2 = fminf(fmaxf(p2, -2.f), 2.f) + 2.f;
        int i1 = (int)floorf(p1), i2 = (int)floorf(p2);
        float r1 = p1 - (float)i1, r2 = p2 - (float)i2;
        acc[i1 * 5 + i2] += ww * (1.f - r1) * (1.f - r2);
        if (i1 + 1 < 5)               acc[(i1 + 1) * 5 + i2]     += ww * r1 * (1.f - r2);
        if (i2 + 1 < 5)               acc[i1 * 5 + (i2 + 1)]     += ww * (1.f - r1) * r2;
        if (i1 + 1 < 5 && i2 + 1 < 5) acc[(i1 + 1) * 5 + i2 + 1] += ww * r1 * r2;
    }
    if (layer == 0) {
        float* o = g_K1 + t * 32;
#pragma unroll
        for (int j = 0; j < 32; j++) o[j] = (j < 25) ? acc[j] : 0.f;
    } else {
        int co = t >> 5;          // Ci = 32
        int ci = t & 31;
        int cog = co >> 2;        // 0..15
        int c   = (co >> 1) & 1;  // pair-within-group
        int e   = co & 1;         // lane parity within pair
#pragma unroll
        for (int j = 0; j < 25; j++)
            g_K2w[((ci * 25 + j) * 2 + c) * 32 + cog * 2 + e] = acc[j];
    }
}

// ---------------- conv1 (1->32, 5x5, pad2) + bias + relu + maxpool2 ---------
__global__ __launch_bounds__(256) void conv1_pool(const float* __restrict__ x,
                                                  const float* __restrict__ b1) {
    __shared__ float s_in[32 * 33];
    __shared__ float s_w[32 * 32];
    int b = blockIdx.x;
    int tid = threadIdx.x;
    for (int i = tid; i < 32 * 33; i += 256) s_in[i] = 0.f;
    for (int i = tid; i < 32 * 32; i += 256) s_w[i] = g_K1[i];
    __syncthreads();
    const float* xb = x + b * 784;
    for (int i = tid; i < 784; i += 256) {
        int y = i / 28, xx = i - y * 28;
        s_in[(y + 2) * 33 + (xx + 2)] = xb[i];
    }
    __syncthreads();

    int co = tid >> 3;
    int s  = tid & 7;
    float wreg[25];
#pragma unroll
    for (int j = 0; j < 25; j++) wreg[j] = s_w[co * 32 + j];
    float bias = b1[co];
    float* ob = g_out1 + (b * 32 + co) * 196;

    for (int pos = s; pos < 196; pos += 8) {
        int oy = pos / 14, ox = pos - oy * 14;
        const float* pbase = s_in + (2 * oy) * 33 + 2 * ox;
        float xin[6][6];
#pragma unroll
        for (int r = 0; r < 6; r++)
#pragma unroll
            for (int c = 0; c < 6; c++) xin[r][c] = pbase[r * 33 + c];
        float a00 = 0.f, a01 = 0.f, a10 = 0.f, a11 = 0.f;
#pragma unroll
        for (int ky = 0; ky < 5; ky++)
#pragma unroll
            for (int kx = 0; kx < 5; kx++) {
                float w = wreg[ky * 5 + kx];
                a00 = fmaf(w, xin[ky][kx],         a00);
                a01 = fmaf(w, xin[ky][kx + 1],     a01);
                a10 = fmaf(w, xin[ky + 1][kx],     a10);
                a11 = fmaf(w, xin[ky + 1][kx + 1], a11);
            }
        float m = fmaxf(fmaxf(a00, a01), fmaxf(a10, a11));
        ob[pos] = fmaxf(m + bias, 0.f);
    }
}

// ---------------- conv2 (32->64) f32x2, smem-staged weights -----------------
// 448 threads = 14 warps. lane = cog*2 + ps; pixel pp = warp*2+ps.
// Input: undup smem, LDS.128 (2 addrs/warp, conflict-free), dup to (v,v) in regs.
// Weights: per-ci 6.4KB slice staged to smem (double-buffered, prefetch 1 ahead);
// compute reads are conflict-free LDS.64 broadcasts.
__device__ __forceinline__ void loadx(ull* D, const float* xp, int R) {
    float4 a = *(const float4*)(xp + R * 20);
    float4 b = *(const float4*)(xp + R * 20 + 4);
    D[0] = dup2(a.x); D[1] = dup2(a.y); D[2] = dup2(a.z); D[3] = dup2(a.w);
    D[4] = dup2(b.x); D[5] = dup2(b.y); D[6] = dup2(b.z); D[7] = dup2(b.w);
}
__device__ __forceinline__ void loadw(ull W[2][5], const float* wp, int KY) {
#pragma unroll
    for (int kx = 0; kx < 5; kx++) {
        W[0][kx] = *(const ull*)(wp + ((KY * 5 + kx) * 2 + 0) * 32);
        W[1][kx] = *(const ull*)(wp + ((KY * 5 + kx) * 2 + 1) * 32);
    }
}
__device__ __forceinline__ void fmas(ull acc[2][8], ull W[2][5], ull* R0, ull* R1) {
#pragma unroll
    for (int kx = 0; kx < 5; kx++)
#pragma unroll
        for (int cx = 0; cx < 4; cx++) {
            acc[0][cx]     = ffma2(W[0][kx], R0[cx + kx], acc[0][cx]);
            acc[1][cx]     = ffma2(W[1][kx], R0[cx + kx], acc[1][cx]);
            acc[0][4 + cx] = ffma2(W[0][kx], R1[cx + kx], acc[0][4 + cx]);
            acc[1][4 + cx] = ffma2(W[1][kx], R1[cx + kx], acc[1][4 + cx]);
        }
}

__global__ __launch_bounds__(448, 1) void conv2_pool(const float* __restrict__ b2) {
    extern __shared__ float smem[];
    float* s_in = smem;                 // 32*18*20 = 11520 floats (46080B)
    float* s_w0 = smem + 11520;         // 1600 floats
    float* s_w1 = smem + 11520 + 1600;  // 1600 floats ; total 58880B
    int b = blockIdx.x;
    int tid = threadIdx.x;

    for (int i = tid; i < 32 * 18 * 20; i += 448) s_in[i] = 0.f;
    // preload weights for ci=0 into buffer 0
    if (tid < 400) ((float4*)s_w0)[tid] = ((const float4*)g_K2w)[tid];
    __syncthreads();
    const float* inb = g_out1 + b * 6272;
    for (int i = tid; i < 6272; i += 448) {
        int ci = i / 196;
        int r = i - ci * 196;
        int y = r / 14, xx = r - y * 14;
        s_in[ci * 360 + (y + 2) * 20 + (xx + 2)] = inb[i];
    }
    __syncthreads();

    int wrp  = tid >> 5;          // 0..13
    int lane = tid & 31;
    int cog  = lane >> 1;         // 0..15
    int ps   = lane & 1;
    int pp   = wrp * 2 + ps;      // 0..27
    int oy   = pp >> 2;           // 0..6
    int oxp  = pp & 3;            // 0..3

    ull acc[2][8];
#pragma unroll
    for (int c = 0; c < 2; c++)
#pragma unroll
        for (int j = 0; j < 8; j++) acc[c][j] = 0ull;

    const float* xbase = s_in + (2 * oy) * 20 + oxp * 4;

#pragma unroll 1
    for (int ci = 0; ci < 32; ci++) {
        // prefetch next ci's weight slice into the other buffer
        if (ci + 1 < 32 && tid < 400) {
            float4 v = ((const float4*)g_K2w)[(ci + 1) * 400 + tid];
            ((float4*)((ci & 1) ? s_w0 : s_w1))[tid] = v;
        }
        const float* xp = xbase + ci * 360;
        const float* wp = ((ci & 1) ? s_w1 : s_w0) + cog * 2;
        ull xA[8], xB[8], wA[2][5], wB[2][5];
        loadx(xA, xp, 0); loadw(wA, wp, 0);
        loadx(xB, xp, 1); loadw(wB, wp, 1);
        fmas(acc, wA, xA, xB);            // ky=0: rows 0,1
        loadx(xA, xp, 2); loadw(wA, wp, 2);
        fmas(acc, wB, xB, xA);            // ky=1: rows 1,2
        loadx(xB, xp, 3); loadw(wB, wp, 3);
        fmas(acc, wA, xA, xB);            // ky=2: rows 2,3
        loadx(xA, xp, 4); loadw(wA, wp, 4);
        fmas(acc, wB, xB, xA);            // ky=3: rows 3,4
        loadx(xB, xp, 5);
        fmas(acc, wA, xA, xB);            // ky=4: rows 4,5
        __syncthreads();                  // buffer handoff
    }

    // bias + relu + 2x2 maxpool; acc lanes: .x = co even, .y = co odd
    int b64 = b * 64;
#pragma unroll
    for (int c = 0; c < 2; c++) {
        int co_e = cog * 4 + c * 2;
        float be = b2[co_e], bo = b2[co_e + 1];
#pragma unroll
        for (int px = 0; px < 2; px++) {
            int ox = 2 * oxp + px;
            if (ox < 7) {
                float2 v0 = *(float2*)&acc[c][2 * px];
                float2 v1 = *(float2*)&acc[c][2 * px + 1];
                float2 v2 = *(float2*)&acc[c][4 + 2 * px];
                float2 v3 = *(float2*)&acc[c][4 + 2 * px + 1];
                float me = fmaxf(fmaxf(v0.x, v1.x), fmaxf(v2.x, v3.x));
                float mo = fmaxf(fmaxf(v0.y, v1.y), fmaxf(v2.y, v3.y));
                g_out2[((b64 + co_e) * 7 + oy) * 7 + ox]     = fmaxf(me + be, 0.f);
                g_out2[((b64 + co_e + 1) * 7 + oy) * 7 + ox] = fmaxf(mo + bo, 0.f);
            }
        }
    }
}

// ---------------- fc1: (4096,3136) x (128,3136)^T + bias, relu -> g_h -------
__global__ __launch_bounds__(256) void fc1_gemm(const float* __restrict__ W,
                                                const float* __restrict__ bias) {
    __shared__ float As[32][64];
    __shared__ float Bs[32][64];
    int tid = threadIdx.x;
    int row0 = blockIdx.x * 64;
    int col0 = blockIdx.y * 64;
    const float* A = g_out2;

    int lr  = tid >> 2;
    int lk4 = (tid & 3) << 3;
    int tm  = tid >> 4;
    int tn  = tid & 15;

    float acc[4][4];
#pragma unroll
    for (int i = 0; i < 4; i++)
#pragma unroll
        for (int j = 0; j < 4; j++) acc[i][j] = 0.f;

    for (int k0 = 0; k0 < 3136; k0 += 32) {
        float4 a0 = *(const float4*)(A + (row0 + lr) * 3136 + k0 + lk4);
        float4 a1 = *(const float4*)(A + (row0 + lr) * 3136 + k0 + lk4 + 4);
        float4 w0 = *(const float4*)(W + (col0 + lr) * 3136 + k0 + lk4);
        float4 w1 = *(const float4*)(W + (col0 + lr) * 3136 + k0 + lk4 + 4);
        __syncthreads();
        As[lk4 + 0][lr] = a0.x; As[lk4 + 1][lr] = a0.y;
        As[lk4 + 2][lr] = a0.z; As[lk4 + 3][lr] = a0.w;
        As[lk4 + 4][lr] = a1.x; As[lk4 + 5][lr] = a1.y;
        As[lk4 + 6][lr] = a1.z; As[lk4 + 7][lr] = a1.w;
        Bs[lk4 + 0][lr] = w0.x; Bs[lk4 + 1][lr] = w0.y;
        Bs[lk4 + 2][lr] = w0.z; Bs[lk4 + 3][lr] = w0.w;
        Bs[lk4 + 4][lr] = w1.x; Bs[lk4 + 5][lr] = w1.y;
        Bs[lk4 + 6][lr] = w1.z; Bs[lk4 + 7][lr] = w1.w;
        __syncthreads();
#pragma unroll
        for (int kk = 0; kk < 32; kk++) {
            float4 av = *(const float4*)&As[kk][tm * 4];
            float4 bv = *(const float4*)&Bs[kk][tn * 4];
            acc[0][0] = fmaf(av.x, bv.x, acc[0][0]);
            acc[0][1] = fmaf(av.x, bv.y, acc[0][1]);
            acc[0][2] = fmaf(av.x, bv.z, acc[0][2]);
            acc[0][3] = fmaf(av.x, bv.w, acc[0][3]);
            acc[1][0] = fmaf(av.y, bv.x, acc[1][0]);
            acc[1][1] = fmaf(av.y, bv.y, acc[1][1]);
            acc[1][2] = fmaf(av.y, bv.z, acc[1][2]);
            acc[1][3] = fmaf(av.y, bv.w, acc[1][3]);
            acc[2][0] = fmaf(av.z, bv.x, acc[2][0]);
            acc[2][1] = fmaf(av.z, bv.y, acc[2][1]);
            acc[2][2] = fmaf(av.z, bv.z, acc[2][2]);
            acc[2][3] = fmaf(av.z, bv.w, acc[2][3]);
            acc[3][0] = fmaf(av.w, bv.x, acc[3][0]);
            acc[3][1] = fmaf(av.w, bv.y, acc[3][1]);
            acc[3][2] = fmaf(av.w, bv.z, acc[3][2]);
            acc[3][3] = fmaf(av.w, bv.w, acc[3][3]);
        }
    }
#pragma unroll
    for (int i = 0; i < 4; i++)
#pragma unroll
        for (int j = 0; j < 4; j++) {
            int rr = row0 + tm * 4 + i;
            int cc = col0 + tn * 4 + j;
            g_h[rr * 128 + cc] = fmaxf(acc[i][j] + bias[cc], 0.f);
        }
}

// ---------------- fc2: (4096,128) x (10,128)^T + bias -> out ----------------
__global__ void fc2_gemv(const float* __restrict__ W, const float* __restrict__ bias,
                         float* __restrict__ out, int B) {
    int idx = blockIdx.x * blockDim.x + threadIdx.x;
    if (idx >= B * 10) return;
    int row = idx / 10;
    int j = idx - row * 10;
    const float* h = g_h + row * 128;
    const float* w = W + j * 128;
    float s = bias[j];
#pragma unroll
    for (int k = 0; k < 128; k += 4) {
        float4 hv = *(const float4*)(h + k);
        float4 wv = *(const float4*)(w + k);
        s = fmaf(hv.x, wv.x, s);
        s = fmaf(hv.y, wv.y, s);
        s = fmaf(hv.z, wv.z, s);
        s = fmaf(hv.w, wv.w, s);
    }
    out[idx] = s;
}

// ---------------- launch -----------------------------------------------------
extern "C" void kernel_launch(void* const* d_in, const int* in_sizes, int n_in,
                              void* d_out, int out_size) {
    const float* x     = (const float*)d_in[0];
    const float* w1    = (const float*)d_in[1];
    const float* p1    = (const float*)d_in[2];
    const float* b1    = (const float*)d_in[3];
    const float* w2    = (const float*)d_in[4];
    const float* p2    = (const float*)d_in[5];
    const float* b2    = (const float*)d_in[6];
    const float* fc1w  = (const float*)d_in[7];
    const float* fc1b  = (const float*)d_in[8];
    const float* fc2w  = (const float*)d_in[9];
    const float* fc2b  = (const float*)d_in[10];
    float* out = (float*)d_out;

    int B = in_sizes[0] / 784;   // 4096
    const int smem2 = (32 * 18 * 20 + 2 * 1600) * 4;   // 58880 B

    static int attr_done = 0;
    if (!attr_done) {
        cudaFuncSetAttribute(conv2_pool, cudaFuncAttributeMaxDynamicSharedMemorySize, smem2);
        attr_done = 1;
    }

    build_dcls<<<1, 64>>>(w1, p1, 32, 1, 16, 0);
    build_dcls<<<8, 256>>>(w2, p2, 64, 32, 32, 1);
    conv1_pool<<<B, 256>>>(x, b1);
    conv2_pool<<<B, 448, smem2>>>(b2);
    dim3 g1(B / 64, 2);
    fc1_gemm<<<g1, 256>>>(fc1w, fc1b);
    fc2_gemv<<<(B * 10 + 255) / 256, 256>>>(fc2w, fc2b, out, B);
}

// round 14
// speedup vs baseline: 1.3379x; 1.1777x over previous
#include <cuda_runtime.h>
#include <math.h>

typedef unsigned long long ull;

// ---------------- scratch (device globals; no allocs allowed) ----------------
__device__ float g_K1[32 * 32];               // [co][tap32] (25 used, padded)
__device__ float g_K2w[32 * 25 * 2 * 32];     // [ci][tap][c][cog][2] pair layout
__device__ float g_out1[4096 * 32 * 14 * 14]; // conv1+pool output
__device__ float g_out2[4096 * 64 * 7 * 7];   // conv2+pool output (= fc1 input)
__device__ float g_h[4096 * 128];             // fc1 output

__device__ __forceinline__ ull ffma2(ull a, ull b, ull c) {
    ull d;
    asm("fma.rn.f32x2 %0, %1, %2, %3;" : "=l"(d) : "l"(a), "l"(b), "l"(c));
    return d;
}
__device__ __forceinline__ ull dup2(float v) {
    float2 t = make_float2(v, v);
    return *reinterpret_cast<ull*>(&t);
}

// ---------------- DCLS kernel construction (gather, deterministic) ----------
__global__ void build_dcls(const float* __restrict__ w, const float* __restrict__ p,
                           int Co, int Ci, int Kc, int layer) {
    int t = blockIdx.x * blockDim.x + threadIdx.x;
    if (t >= Co * Ci) return;
    float acc[25];
#pragma unroll
    for (int j = 0; j < 25; j++) acc[j] = 0.f;
    int base = t * Kc;
    int pstride = Co * Ci * Kc;
    for (int kc = 0; kc < Kc; kc++) {
        float ww = w[base + kc];
        float p1 = p[base + kc];
        float p2 = p[pstride + base + kc];
        p1 = fminf(fmaxf(p1, -2.f), 2.f) + 2.f;
        p2 = fminf(fmaxf(p2, -2.f), 2.f) + 2.f;
        int i1 = (int)floorf(p1), i2 = (int)floorf(p2);
        float r1 = p1 - (float)i1, r2 = p2 - (float)i2;
        acc[i1 * 5 + i2] += ww * (1.f - r1) * (1.f - r2);
        if (i1 + 1 < 5)               acc[(i1 + 1) * 5 + i2]     += ww * r1 * (1.f - r2);
        if (i2 + 1 < 5)               acc[i1 * 5 + (i2 + 1)]     += ww * (1.f - r1) * r2;
        if (i1 + 1 < 5 && i2 + 1 < 5) acc[(i1 + 1) * 5 + i2 + 1] += ww * r1 * r2;
    }
    if (layer == 0) {
        float* o = g_K1 + t * 32;
#pragma unroll
        for (int j = 0; j < 32; j++) o[j] = (j < 25) ? acc[j] : 0.f;
    } else {
        int co = t >> 5;          // Ci = 32
        int ci = t & 31;
        int cog = co >> 2;        // 0..15
        int c   = (co >> 1) & 1;  // pair-within-group
        int e   = co & 1;         // lane parity within pair
#pragma unroll
        for (int j = 0; j < 25; j++)
            g_K2w[((ci * 25 + j) * 2 + c) * 32 + cog * 2 + e] = acc[j];
    }
}

// ---------------- conv1 (1->32, 5x5, pad2) + bias + relu + maxpool2 ---------
__global__ __launch_bounds__(256) void conv1_pool(const float* __restrict__ x,
                                                  const float* __restrict__ b1) {
    __shared__ float s_in[32 * 33];
    __shared__ float s_w[32 * 32];
    int b = blockIdx.x;
    int tid = threadIdx.x;
    for (int i = tid; i < 32 * 33; i += 256) s_in[i] = 0.f;
    for (int i = tid; i < 32 * 32; i += 256) s_w[i] = g_K1[i];
    __syncthreads();
    const float* xb = x + b * 784;
    for (int i = tid; i < 784; i += 256) {
        int y = i / 28, xx = i - y * 28;
        s_in[(y + 2) * 33 + (xx + 2)] = xb[i];
    }
    __syncthreads();

    int co = tid >> 3;
    int s  = tid & 7;
    float wreg[25];
#pragma unroll
    for (int j = 0; j < 25; j++) wreg[j] = s_w[co * 32 + j];
    float bias = b1[co];
    float* ob = g_out1 + (b * 32 + co) * 196;

    for (int pos = s; pos < 196; pos += 8) {
        int oy = pos / 14, ox = pos - oy * 14;
        const float* pbase = s_in + (2 * oy) * 33 + 2 * ox;
        float xin[6][6];
#pragma unroll
        for (int r = 0; r < 6; r++)
#pragma unroll
            for (int c = 0; c < 6; c++) xin[r][c] = pbase[r * 33 + c];
        float a00 = 0.f, a01 = 0.f, a10 = 0.f, a11 = 0.f;
#pragma unroll
        for (int ky = 0; ky < 5; ky++)
#pragma unroll
            for (int kx = 0; kx < 5; kx++) {
                float w = wreg[ky * 5 + kx];
                a00 = fmaf(w, xin[ky][kx],         a00);
                a01 = fmaf(w, xin[ky][kx + 1],     a01);
                a10 = fmaf(w, xin[ky + 1][kx],     a10);
                a11 = fmaf(w, xin[ky + 1][kx + 1], a11);
            }
        float m = fmaxf(fmaxf(a00, a01), fmaxf(a10, a11));
        ob[pos] = fmaxf(m + bias, 0.f);
    }
}

// ---------------- conv2 (32->64) f32x2, smem weights, 2 CTAs/SM -------------
// 448 threads = 14 warps; 2 CTAs/SM (7 warps/SMSP) to hide LDS/BAR latency.
// lane = cog*2 + ps; pixel pp = warp*2+ps.
// Input: undup smem, LDS.128 (2 addrs/warp), dup to (v,v) in regs.
// Weights: per-ci 6.4KB smem slice (double-buffered, prefetch 1 ahead);
// inline per-kx LDS.64 broadcasts (only 2 weight regs live -> fits 72-reg cap).
__device__ __forceinline__ void loadx(ull* D, const float* xp, int R) {
    float4 a = *(const float4*)(xp + R * 20);
    float4 b = *(const float4*)(xp + R * 20 + 4);
    D[0] = dup2(a.x); D[1] = dup2(a.y); D[2] = dup2(a.z); D[3] = dup2(a.w);
    D[4] = dup2(b.x); D[5] = dup2(b.y); D[6] = dup2(b.z); D[7] = dup2(b.w);
}
// one ky band: rows R0 (conv row 0) and R1 (conv row 1), weights loaded per-kx
__device__ __forceinline__ void band(ull acc[2][8], const float* wp, int KY,
                                     ull* R0, ull* R1) {
#pragma unroll
    for (int kx = 0; kx < 5; kx++) {
        ull W0 = *(const ull*)(wp + ((KY * 5 + kx) * 2 + 0) * 32);
        ull W1 = *(const ull*)(wp + ((KY * 5 + kx) * 2 + 1) * 32);
#pragma unroll
        for (int cx = 0; cx < 4; cx++) {
            acc[0][cx]     = ffma2(W0, R0[cx + kx], acc[0][cx]);
            acc[1][cx]     = ffma2(W1, R0[cx + kx], acc[1][cx]);
            acc[0][4 + cx] = ffma2(W0, R1[cx + kx], acc[0][4 + cx]);
            acc[1][4 + cx] = ffma2(W1, R1[cx + kx], acc[1][4 + cx]);
        }
    }
}

__global__ __launch_bounds__(448, 2) void conv2_pool(const float* __restrict__ b2) {
    extern __shared__ float smem[];
    float* s_in = smem;                 // 32*18*20 = 11520 floats (46080B)
    float* s_w0 = smem + 11520;         // 1600 floats
    float* s_w1 = smem + 11520 + 1600;  // 1600 floats ; total 58880B
    int b = blockIdx.x;
    int tid = threadIdx.x;

    for (int i = tid; i < 32 * 18 * 20; i += 448) s_in[i] = 0.f;
    if (tid < 400) ((float4*)s_w0)[tid] = ((const float4*)g_K2w)[tid];
    __syncthreads();
    const float* inb = g_out1 + b * 6272;
    for (int i = tid; i < 6272; i += 448) {
        int ci = i / 196;
        int r = i - ci * 196;
        int y = r / 14, xx = r - y * 14;
        s_in[ci * 360 + (y + 2) * 20 + (xx + 2)] = inb[i];
    }
    __syncthreads();

    int wrp  = tid >> 5;          // 0..13
    int lane = tid & 31;
    int cog  = lane >> 1;         // 0..15
    int ps   = lane & 1;
    int pp   = wrp * 2 + ps;      // 0..27
    int oy   = pp >> 2;           // 0..6
    int oxp  = pp & 3;            // 0..3

    ull acc[2][8];
#pragma unroll
    for (int c = 0; c < 2; c++)
#pragma unroll
        for (int j = 0; j < 8; j++) acc[c][j] = 0ull;

    const float* xbase = s_in + (2 * oy) * 20 + oxp * 4;

#pragma unroll 1
    for (int ci = 0; ci < 32; ci++) {
        if (ci + 1 < 32 && tid < 400) {
            float4 v = ((const float4*)g_K2w)[(ci + 1) * 400 + tid];
            ((float4*)((ci & 1) ? s_w0 : s_w1))[tid] = v;
        }
        const float* xp = xbase + ci * 360;
        const float* wp = ((ci & 1) ? s_w1 : s_w0) + cog * 2;
        ull xA[8], xB[8];
        loadx(xA, xp, 0);
        loadx(xB, xp, 1);
        band(acc, wp, 0, xA, xB);          // ky=0: rows 0,1
        loadx(xA, xp, 2);
        band(acc, wp, 1, xB, xA);          // ky=1: rows 1,2
        loadx(xB, xp, 3);
        band(acc, wp, 2, xA, xB);          // ky=2: rows 2,3
        loadx(xA, xp, 4);
        band(acc, wp, 3, xB, xA);          // ky=3: rows 3,4
        loadx(xB, xp, 5);
        band(acc, wp, 4, xA, xB);          // ky=4: rows 4,5
        __syncthreads();                   // buffer handoff
    }

    // bias + relu + 2x2 maxpool; acc lanes: .x = co even, .y = co odd
    int b64 = b * 64;
#pragma unroll
    for (int c = 0; c < 2; c++) {
        int co_e = cog * 4 + c * 2;
        float be = b2[co_e], bo = b2[co_e + 1];
#pragma unroll
        for (int px = 0; px < 2; px++) {
            int ox = 2 * oxp + px;
            if (ox < 7) {
                float2 v0 = *(float2*)&acc[c][2 * px];
                float2 v1 = *(float2*)&acc[c][2 * px + 1];
                float2 v2 = *(float2*)&acc[c][4 + 2 * px];
                float2 v3 = *(float2*)&acc[c][4 + 2 * px + 1];
                float me = fmaxf(fmaxf(v0.x, v1.x), fmaxf(v2.x, v3.x));
                float mo = fmaxf(fmaxf(v0.y, v1.y), fmaxf(v2.y, v3.y));
                g_out2[((b64 + co_e) * 7 + oy) * 7 + ox]     = fmaxf(me + be, 0.f);
                g_out2[((b64 + co_e + 1) * 7 + oy) * 7 + ox] = fmaxf(mo + bo, 0.f);
            }
        }
    }
}

// ---------------- fc1: (4096,3136) x (128,3136)^T + bias, relu -> g_h -------
__global__ __launch_bounds__(256) void fc1_gemm(const float* __restrict__ W,
                                                const float* __restrict__ bias) {
    __shared__ float As[32][64];
    __shared__ float Bs[32][64];
    int tid = threadIdx.x;
    int row0 = blockIdx.x * 64;
    int col0 = blockIdx.y * 64;
    const float* A = g_out2;

    int lr  = tid >> 2;
    int lk4 = (tid & 3) << 3;
    int tm  = tid >> 4;
    int tn  = tid & 15;

    float acc[4][4];
#pragma unroll
    for (int i = 0; i < 4; i++)
#pragma unroll
        for (int j = 0; j < 4; j++) acc[i][j] = 0.f;

    for (int k0 = 0; k0 < 3136; k0 += 32) {
        float4 a0 = *(const float4*)(A + (row0 + lr) * 3136 + k0 + lk4);
        float4 a1 = *(const float4*)(A + (row0 + lr) * 3136 + k0 + lk4 + 4);
        float4 w0 = *(const float4*)(W + (col0 + lr) * 3136 + k0 + lk4);
        float4 w1 = *(const float4*)(W + (col0 + lr) * 3136 + k0 + lk4 + 4);
        __syncthreads();
        As[lk4 + 0][lr] = a0.x; As[lk4 + 1][lr] = a0.y;
        As[lk4 + 2][lr] = a0.z; As[lk4 + 3][lr] = a0.w;
        As[lk4 + 4][lr] = a1.x; As[lk4 + 5][lr] = a1.y;
        As[lk4 + 6][lr] = a1.z; As[lk4 + 7][lr] = a1.w;
        Bs[lk4 + 0][lr] = w0.x; Bs[lk4 + 1][lr] = w0.y;
        Bs[lk4 + 2][lr] = w0.z; Bs[lk4 + 3][lr] = w0.w;
        Bs[lk4 + 4][lr] = w1.x; Bs[lk4 + 5][lr] = w1.y;
        Bs[lk4 + 6][lr] = w1.z; Bs[lk4 + 7][lr] = w1.w;
        __syncthreads();
#pragma unroll
        for (int kk = 0; kk < 32; kk++) {
            float4 av = *(const float4*)&As[kk][tm * 4];
            float4 bv = *(const float4*)&Bs[kk][tn * 4];
            acc[0][0] = fmaf(av.x, bv.x, acc[0][0]);
            acc[0][1] = fmaf(av.x, bv.y, acc[0][1]);
            acc[0][2] = fmaf(av.x, bv.z, acc[0][2]);
            acc[0][3] = fmaf(av.x, bv.w, acc[0][3]);
            acc[1][0] = fmaf(av.y, bv.x, acc[1][0]);
            acc[1][1] = fmaf(av.y, bv.y, acc[1][1]);
            acc[1][2] = fmaf(av.y, bv.z, acc[1][2]);
            acc[1][3] = fmaf(av.y, bv.w, acc[1][3]);
            acc[2][0] = fmaf(av.z, bv.x, acc[2][0]);
            acc[2][1] = fmaf(av.z, bv.y, acc[2][1]);
            acc[2][2] = fmaf(av.z, bv.z, acc[2][2]);
            acc[2][3] = fmaf(av.z, bv.w, acc[2][3]);
            acc[3][0] = fmaf(av.w, bv.x, acc[3][0]);
            acc[3][1] = fmaf(av.w, bv.y, acc[3][1]);
            acc[3][2] = fmaf(av.w, bv.z, acc[3][2]);
            acc[3][3] = fmaf(av.w, bv.w, acc[3][3]);
        }
    }
#pragma unroll
    for (int i = 0; i < 4; i++)
#pragma unroll
        for (int j = 0; j < 4; j++) {
            int rr = row0 + tm * 4 + i;
            int cc = col0 + tn * 4 + j;
            g_h[rr * 128 + cc] = fmaxf(acc[i][j] + bias[cc], 0.f);
        }
}

// ---------------- fc2: (4096,128) x (10,128)^T + bias -> out ----------------
__global__ void fc2_gemv(const float* __restrict__ W, const float* __restrict__ bias,
                         float* __restrict__ out, int B) {
    int idx = blockIdx.x * blockDim.x + threadIdx.x;
    if (idx >= B * 10) return;
    int row = idx / 10;
    int j = idx - row * 10;
    const float* h = g_h + row * 128;
    const float* w = W + j * 128;
    float s = bias[j];
#pragma unroll
    for (int k = 0; k < 128; k += 4) {
        float4 hv = *(const float4*)(h + k);
        float4 wv = *(const float4*)(w + k);
        s = fmaf(hv.x, wv.x, s);
        s = fmaf(hv.y, wv.y, s);
        s = fmaf(hv.z, wv.z, s);
        s = fmaf(hv.w, wv.w, s);
    }
    out[idx] = s;
}

// ---------------- launch -----------------------------------------------------
extern "C" void kernel_launch(void* const* d_in, const int* in_sizes, int n_in,
                              void* d_out, int out_size) {
    const float* x     = (const float*)d_in[0];
    const float* w1    = (const float*)d_in[1];
    const float* p1    = (const float*)d_in[2];
    const float* b1    = (const float*)d_in[3];
    const float* w2    = (const float*)d_in[4];
    const float* p2    = (const float*)d_in[5];
    const float* b2    = (const float*)d_in[6];
    const float* fc1w  = (const float*)d_in[7];
    const float* fc1b  = (const float*)d_in[8];
    const float* fc2w  = (const float*)d_in[9];
    const float* fc2b  = (const float*)d_in[10];
    float* out = (float*)d_out;

    int B = in_sizes[0] / 784;   // 4096
    const int smem2 = (32 * 18 * 20 + 2 * 1600) * 4;   // 58880 B

    static int attr_done = 0;
    if (!attr_done) {
        cudaFuncSetAttribute(conv2_pool, cudaFuncAttributeMaxDynamicSharedMemorySize, smem2);
        attr_done = 1;
    }

    build_dcls<<<1, 64>>>(w1, p1, 32, 1, 16, 0);
    build_dcls<<<8, 256>>>(w2, p2, 64, 32, 32, 1);
    conv1_pool<<<B, 256>>>(x, b1);
    conv2_pool<<<B, 448, smem2>>>(b2);
    dim3 g1(B / 64, 2);
    fc1_gemm<<<g1, 256>>>(fc1w, fc1b);
    fc2_gemv<<<(B * 10 + 255) / 256, 256>>>(fc2w, fc2b, out, B);
}